// round 12
// baseline (speedup 1.0000x reference)
#include <cuda_runtime.h>
#include <cuda_fp16.h>
#include <cuda_bf16.h>

#define Nn 50000
#define Ne 800000
// IN=128, H1=8, HID=32, OUT=64

// ---------------- device scratch ----------------
__device__ __half g_h1h[(size_t)Nn * 256];  // layer1 features fp16 [N,8,32]
__device__ float g_x1[(size_t)Nn * 256];    // layer1 output (relu) = layer2 input
__device__ float g_el1[Nn * 8], g_er1[Nn * 8];
__device__ __half g_h2h[(size_t)Nn * 32];
__device__ float g_el2[Nn], g_er2[Nn];
__device__ __half g_h3h[(size_t)Nn * 64];
__device__ float g_el3[Nn], g_er3[Nn];

__device__ int g_deg[Nn];
__device__ int g_fill[Nn];
__device__ int g_rowstart[Nn + 1];
__device__ int g_esrc[Ne];

__device__ unsigned g_wpk[128 * 256];      // W1 packed bf16 hi|lo
__device__ unsigned g_wpk2[256 * 32];      // W2 packed bf16 hi|lo

// ---------------- helpers ----------------
__device__ __forceinline__ float wred(float v) {
#pragma unroll
    for (int o = 16; o > 0; o >>= 1) v += __shfl_xor_sync(0xffffffffu, v, o);
    return v;
}

__device__ __forceinline__ float lrelu(float x) {
    return x > 0.f ? x : 0.2f * x;
}

__device__ __forceinline__ void mma16816(float c[4], unsigned a0, unsigned a1,
                                         unsigned a2, unsigned a3,
                                         unsigned b0, unsigned b1) {
    asm volatile(
        "mma.sync.aligned.m16n8k16.row.col.f32.bf16.bf16.f32 "
        "{%0,%1,%2,%3}, {%4,%5,%6,%7}, {%8,%9}, {%0,%1,%2,%3};\n"
        : "+f"(c[0]), "+f"(c[1]), "+f"(c[2]), "+f"(c[3])
        : "r"(a0), "r"(a1), "r"(a2), "r"(a3), "r"(b0), "r"(b1));
}

__device__ __forceinline__ unsigned packw(float v) {
    __nv_bfloat16 h = __float2bfloat16(v);
    float hf = __bfloat162float(h);
    __nv_bfloat16 l = __float2bfloat16(v - hf);
    return (unsigned)__bfloat16_as_ushort(h) | ((unsigned)__bfloat16_as_ushort(l) << 16);
}

// ---------------- CSR build ----------------
__global__ void zero_kernel() {
    int i = blockIdx.x * blockDim.x + threadIdx.x;
    if (i < Nn) { g_deg[i] = 0; g_fill[i] = 0; }
}

__global__ void count_kernel(const int* __restrict__ dst) {
    int e = blockIdx.x * blockDim.x + threadIdx.x;
    if (e < Ne) atomicAdd(&g_deg[dst[e]], 1);
}

__global__ void scan_kernel() {
    __shared__ int warpsum[32];
    const int t = threadIdx.x;            // 1024
    const int lane = t & 31, wid = t >> 5;
    const int CH = (Nn + 1023) / 1024;
    const int base = t * CH;
    int sum = 0;
#pragma unroll 1
    for (int i = 0; i < CH; i++) {
        int idx = base + i;
        if (idx < Nn) sum += g_deg[idx];
    }
    int v = sum;
#pragma unroll
    for (int o = 1; o < 32; o <<= 1) {
        int u = __shfl_up_sync(0xffffffffu, v, o);
        if (lane >= o) v += u;
    }
    if (lane == 31) warpsum[wid] = v;
    __syncthreads();
    if (wid == 0) {
        int w = warpsum[lane];
        int vv = w;
#pragma unroll
        for (int o = 1; o < 32; o <<= 1) {
            int u = __shfl_up_sync(0xffffffffu, vv, o);
            if (lane >= o) vv += u;
        }
        warpsum[lane] = vv;
    }
    __syncthreads();
    int excl = v - sum + (wid > 0 ? warpsum[wid - 1] : 0);
    int run = excl;
#pragma unroll 1
    for (int i = 0; i < CH; i++) {
        int idx = base + i;
        if (idx < Nn) { g_rowstart[idx] = run; run += g_deg[idx]; }
    }
    if (t == 1023) g_rowstart[Nn] = run;
}

__global__ void scatter_kernel(const int* __restrict__ src, const int* __restrict__ dst) {
    int e = blockIdx.x * blockDim.x + threadIdx.x;
    if (e >= Ne) return;
    int d = dst[e];
    int pos = g_rowstart[d] + atomicAdd(&g_fill[d], 1);
    g_esrc[pos] = src[e];
}

// ---------------- W packing (bf16 hi/lo), both weights ----------------
__global__ void wpack_kernel(const float* __restrict__ W1, const float* __restrict__ W2) {
    int i = blockIdx.x * blockDim.x + threadIdx.x;   // 40960
    float w;
    if (i < 32768) w = W1[i];
    else           w = W2[i - 32768];
    unsigned p = packw(w);
    if (i < 32768) g_wpk[i] = p;
    else           g_wpk2[i - 32768] = p;
}

// ---------------- layer 1 GEMM: TC bf16-split, compact A, N-split, 2 CTA/SM ----
#define A_STRIDE 132           // bank(4g+tr) conflict-free for A frag loads
#define B1_STRIDE 136          // bank(8tr+g) conflict-free for B frag loads
#define G1_SMEM ((64 * A_STRIDE + 128 * B1_STRIDE) * 4)   // 103424 B

__global__ void __launch_bounds__(256, 2) gemm1m_kernel(const float* __restrict__ X,
                                                        const float* __restrict__ al,
                                                        const float* __restrict__ ar) {
    extern __shared__ unsigned smem[];
    unsigned* Ac = smem;                         // compact (ah|al) [64][A_STRIDE]
    unsigned* B  = smem + 64 * A_STRIDE;         // (bh,bl) [128 k][B1_STRIDE], half N

    const int t = threadIdx.x;
    const int n0 = (blockIdx.x >> 1) * 64;       // row tile
    const int nb = (blockIdx.x & 1) * 128;       // col half

    // stage A: 64 x 128 fp32 -> compact packed words
#pragma unroll
    for (int i = 0; i < 8; i++) {
        int idx = t + 256 * i;                   // float4 index, 2048 total
        int row = idx >> 5, c4 = idx & 31;
        int grow = n0 + row;
        float4 v = (grow < Nn) ? __ldg((const float4*)(X + (size_t)grow * 128) + c4)
                               : make_float4(0.f, 0.f, 0.f, 0.f);
        uint4 p = make_uint4(packw(v.x), packw(v.y), packw(v.z), packw(v.w));
        *(uint4*)&Ac[row * A_STRIDE + c4 * 4] = p;
    }
    // stage B: copy pre-packed W1 columns [nb, nb+128)
#pragma unroll
    for (int i = 0; i < 16; i++) {
        int idx = t + 256 * i;                   // uint4 index, 4096 total
        int row = idx >> 5, c4 = idx & 31;
        uint4 v = *((const uint4*)(g_wpk + row * 256 + nb) + c4);
        *(uint4*)&B[row * B1_STRIDE + c4 * 4] = v;
    }
    __syncthreads();

    const int warp = t >> 5, lane = t & 31;
    const int wm = warp >> 2, wn = warp & 3;     // 2 (M:32 rows) x 4 (N:32 cols)
    const int g = lane >> 2, tr = lane & 3;

    float c[2][4][4] = {};
#pragma unroll 1
    for (int ks = 0; ks < 16; ks++) {
        int kb = ks * 8;
        unsigned b0[4], b1[4];
#pragma unroll
        for (int nt = 0; nt < 4; nt++) {
            int colL = wn * 32 + nt * 8 + g;
            b0[nt] = B[(kb + tr) * B1_STRIDE + colL];
            b1[nt] = B[(kb + 4 + tr) * B1_STRIDE + colL];
        }
#pragma unroll
        for (int mt = 0; mt < 2; mt++) {
            int rb = wm * 32 + mt * 16;
            unsigned aw0 = Ac[(rb + g) * A_STRIDE + kb + tr];
            unsigned aw1 = Ac[(rb + 8 + g) * A_STRIDE + kb + tr];
            unsigned aw2 = Ac[(rb + g) * A_STRIDE + kb + 4 + tr];
            unsigned aw3 = Ac[(rb + 8 + g) * A_STRIDE + kb + 4 + tr];
            // hi pass: (ah,ah) x (bh,bl)
            unsigned h0 = __byte_perm(aw0, aw0, 0x1010);
            unsigned h1 = __byte_perm(aw1, aw1, 0x1010);
            unsigned h2 = __byte_perm(aw2, aw2, 0x1010);
            unsigned h3 = __byte_perm(aw3, aw3, 0x1010);
#pragma unroll
            for (int nt = 0; nt < 4; nt++)
                mma16816(c[mt][nt], h0, h1, h2, h3, b0[nt], b1[nt]);
            // lo pass: (al,al) x (bh,bl)
            unsigned l0 = __byte_perm(aw0, aw0, 0x3232);
            unsigned l1 = __byte_perm(aw1, aw1, 0x3232);
            unsigned l2 = __byte_perm(aw2, aw2, 0x3232);
            unsigned l3 = __byte_perm(aw3, aw3, 0x3232);
#pragma unroll
            for (int nt = 0; nt < 4; nt++)
                mma16816(c[mt][nt], l0, l1, l2, l3, b0[nt], b1[nt]);
        }
    }

    // epilogue: store fp16 h1 + per-head el/er (this warp = head (nb/32 + wn))
    const int head = (nb >> 5) + wn;
    float alv[4][2], arv[4][2];
#pragma unroll
    for (int nt = 0; nt < 4; nt++) {
        int col = nb + wn * 32 + nt * 8 + tr * 2;
        alv[nt][0] = __ldg(al + col);  alv[nt][1] = __ldg(al + col + 1);
        arv[nt][0] = __ldg(ar + col);  arv[nt][1] = __ldg(ar + col + 1);
    }
#pragma unroll
    for (int mt = 0; mt < 2; mt++) {
#pragma unroll
        for (int half = 0; half < 2; half++) {
            int r = n0 + wm * 32 + mt * 16 + g + 8 * half;
            float pe = 0.f, pr = 0.f;
#pragma unroll
            for (int nt = 0; nt < 4; nt++) {
                float c0 = c[mt][nt][2 * half], c1 = c[mt][nt][2 * half + 1];
                int col = nb + wn * 32 + nt * 8 + tr * 2;
                if (r < Nn)
                    *(__half2*)&g_h1h[(size_t)r * 256 + col] = __floats2half2_rn(c0, c1);
                pe += c0 * alv[nt][0] + c1 * alv[nt][1];
                pr += c0 * arv[nt][0] + c1 * arv[nt][1];
            }
            pe += __shfl_xor_sync(0xffffffffu, pe, 1);
            pe += __shfl_xor_sync(0xffffffffu, pe, 2);
            pr += __shfl_xor_sync(0xffffffffu, pr, 1);
            pr += __shfl_xor_sync(0xffffffffu, pr, 2);
            if (tr == 0 && r < Nn) {
                g_el1[r * 8 + head] = pe;
                g_er1[r * 8 + head] = pr;
            }
        }
    }
}

// ---------------- layer 1 aggregation: warp/dst, 4x unrolled gather --------
__global__ void agg1_kernel(const float* __restrict__ b1) {
    const int wid = (blockIdx.x * blockDim.x + threadIdx.x) >> 5;
    const int lane = threadIdx.x & 31;
    const int d = wid;
    const int rs = g_rowstart[d], re = g_rowstart[d + 1];
    const float erh = (lane < 8) ? g_er1[d * 8 + lane] : 0.f;
    const int h0 = lane >> 4;
    float2 acc[4] = {{0, 0}, {0, 0}, {0, 0}, {0, 0}};
    float s = 0.f;
    int e = rs;
    for (; e + 4 <= re; e += 4) {
        int s0 = g_esrc[e], s1 = g_esrc[e + 1], s2 = g_esrc[e + 2], s3 = g_esrc[e + 3];
        float l0 = 0.f, l1 = 0.f, l2 = 0.f, l3 = 0.f;
        if (lane < 8) {
            l0 = g_el1[s0 * 8 + lane]; l1 = g_el1[s1 * 8 + lane];
            l2 = g_el1[s2 * 8 + lane]; l3 = g_el1[s3 * 8 + lane];
        }
        const __half2* p0 = (const __half2*)(g_h1h + (size_t)s0 * 256);
        const __half2* p1 = (const __half2*)(g_h1h + (size_t)s1 * 256);
        const __half2* p2 = (const __half2*)(g_h1h + (size_t)s2 * 256);
        const __half2* p3 = (const __half2*)(g_h1h + (size_t)s3 * 256);
        __half2 v0[4], v1[4], v2[4], v3[4];
#pragma unroll
        for (int q = 0; q < 4; q++) v0[q] = p0[q * 32 + lane];
#pragma unroll
        for (int q = 0; q < 4; q++) v1[q] = p1[q * 32 + lane];
#pragma unroll
        for (int q = 0; q < 4; q++) v2[q] = p2[q * 32 + lane];
#pragma unroll
        for (int q = 0; q < 4; q++) v3[q] = p3[q * 32 + lane];
        float e0 = 0.f, e1 = 0.f, e2 = 0.f, e3 = 0.f;
        if (lane < 8) {
            e0 = __expf(lrelu(l0 + erh)); e1 = __expf(lrelu(l1 + erh));
            e2 = __expf(lrelu(l2 + erh)); e3 = __expf(lrelu(l3 + erh));
            s += (e0 + e1) + (e2 + e3);
        }
#pragma unroll
        for (int q = 0; q < 4; q++) {
            int hsel = 2 * q + h0;
            float w0 = __shfl_sync(0xffffffffu, e0, hsel);
            float w1 = __shfl_sync(0xffffffffu, e1, hsel);
            float w2 = __shfl_sync(0xffffffffu, e2, hsel);
            float w3 = __shfl_sync(0xffffffffu, e3, hsel);
            float2 f0 = __half22float2(v0[q]), f1 = __half22float2(v1[q]);
            float2 f2 = __half22float2(v2[q]), f3 = __half22float2(v3[q]);
            acc[q].x = fmaf(w0, f0.x, fmaf(w1, f1.x, fmaf(w2, f2.x, fmaf(w3, f3.x, acc[q].x))));
            acc[q].y = fmaf(w0, f0.y, fmaf(w1, f1.y, fmaf(w2, f2.y, fmaf(w3, f3.y, acc[q].y))));
        }
    }
    for (; e < re; e++) {
        int src = g_esrc[e];
        float ee = 0.f;
        if (lane < 8) {
            ee = __expf(lrelu(g_el1[src * 8 + lane] + erh));
            s += ee;
        }
        const __half2* hp = (const __half2*)(g_h1h + (size_t)src * 256);
#pragma unroll
        for (int q = 0; q < 4; q++) {
            float eh = __shfl_sync(0xffffffffu, ee, 2 * q + h0);
            float2 f = __half22float2(hp[q * 32 + lane]);
            acc[q].x = fmaf(eh, f.x, acc[q].x);
            acc[q].y = fmaf(eh, f.y, acc[q].y);
        }
    }
#pragma unroll
    for (int q = 0; q < 4; q++) {
        float sh = __shfl_sync(0xffffffffu, s, 2 * q + h0);
        float inv = (sh > 0.f) ? (1.f / sh) : 0.f;
        int col = 64 * q + 2 * lane;
        float vx = fmaxf(acc[q].x * inv + __ldg(b1 + col), 0.f);
        float vy = fmaxf(acc[q].y * inv + __ldg(b1 + col + 1), 0.f);
        *(float2*)&g_x1[(size_t)d * 256 + col] = make_float2(vx, vy);
    }
}

// ---------------- layer 2 GEMM: TC bf16-split, compact A, 2 CTA/SM ---------
#define A2_STRIDE 260
#define B2_STRIDE 40
#define G2_SMEM ((64 * A2_STRIDE + 256 * B2_STRIDE) * 4)   // 107520 B

__global__ void __launch_bounds__(256, 2) gemm2m_kernel(const float* __restrict__ al,
                                                        const float* __restrict__ ar) {
    extern __shared__ unsigned smem[];
    unsigned* Ac = smem;                         // compact [64][A2_STRIDE]
    unsigned* B  = smem + 64 * A2_STRIDE;        // [256 k][B2_STRIDE]

    const int t = threadIdx.x;
    const int n0 = blockIdx.x * 64;

#pragma unroll
    for (int i = 0; i < 16; i++) {
        int idx = t + 256 * i;                   // float4 index, 4096 total
        int row = idx >> 6, c4 = idx & 63;
        int grow = n0 + row;
        float4 v = (grow < Nn) ? *((const float4*)(g_x1 + (size_t)grow * 256) + c4)
                               : make_float4(0.f, 0.f, 0.f, 0.f);
        uint4 p = make_uint4(packw(v.x), packw(v.y), packw(v.z), packw(v.w));
        *(uint4*)&Ac[row * A2_STRIDE + c4 * 4] = p;
    }
#pragma unroll
    for (int i = 0; i < 8; i++) {
        int idx = t + 256 * i;                   // uint4 index, 2048 total
        int row = idx >> 3, c4 = idx & 7;
        uint4 v = *((const uint4*)g_wpk2 + idx);
        *(uint4*)&B[row * B2_STRIDE + c4 * 4] = v;
    }
    __syncthreads();

    const int warp = t >> 5, lane = t & 31;
    const int wm = warp >> 2, wn = warp & 3;
    const int g = lane >> 2, tr = lane & 3;

    float c[2][4] = {};
#pragma unroll 1
    for (int ks = 0; ks < 32; ks++) {
        int kb = ks * 8;
        int col = wn * 8 + g;
        unsigned b0 = B[(kb + tr) * B2_STRIDE + col];
        unsigned b1 = B[(kb + 4 + tr) * B2_STRIDE + col];
#pragma unroll
        for (int mt = 0; mt < 2; mt++) {
            int rb = wm * 32 + mt * 16;
            unsigned aw0 = Ac[(rb + g) * A2_STRIDE + kb + tr];
            unsigned aw1 = Ac[(rb + 8 + g) * A2_STRIDE + kb + tr];
            unsigned aw2 = Ac[(rb + g) * A2_STRIDE + kb + 4 + tr];
            unsigned aw3 = Ac[(rb + 8 + g) * A2_STRIDE + kb + 4 + tr];
            unsigned h0 = __byte_perm(aw0, aw0, 0x1010);
            unsigned h1 = __byte_perm(aw1, aw1, 0x1010);
            unsigned h2 = __byte_perm(aw2, aw2, 0x1010);
            unsigned h3 = __byte_perm(aw3, aw3, 0x1010);
            mma16816(c[mt], h0, h1, h2, h3, b0, b1);
            unsigned l0 = __byte_perm(aw0, aw0, 0x3232);
            unsigned l1 = __byte_perm(aw1, aw1, 0x3232);
            unsigned l2 = __byte_perm(aw2, aw2, 0x3232);
            unsigned l3 = __byte_perm(aw3, aw3, 0x3232);
            mma16816(c[mt], l0, l1, l2, l3, b0, b1);
        }
    }
    __syncthreads();

    float* epi_e = (float*)smem;          // [64][4]
    float* epi_r = (float*)smem + 256;

    const int col = wn * 8 + tr * 2;
    const float a0v = __ldg(al + col), a1v = __ldg(al + col + 1);
    const float r0v = __ldg(ar + col), r1v = __ldg(ar + col + 1);

#pragma unroll
    for (int mt = 0; mt < 2; mt++) {
#pragma unroll
        for (int half = 0; half < 2; half++) {
            int lrow = wm * 32 + mt * 16 + g + 8 * half;
            int r = n0 + lrow;
            float c0 = c[mt][2 * half], c1 = c[mt][2 * half + 1];
            if (r < Nn)
                *(__half2*)&g_h2h[(size_t)r * 32 + col] = __floats2half2_rn(c0, c1);
            float pe = c0 * a0v + c1 * a1v;
            float pr = c0 * r0v + c1 * r1v;
            pe += __shfl_xor_sync(0xffffffffu, pe, 1);
            pe += __shfl_xor_sync(0xffffffffu, pe, 2);
            pr += __shfl_xor_sync(0xffffffffu, pr, 1);
            pr += __shfl_xor_sync(0xffffffffu, pr, 2);
            if (tr == 0) {
                epi_e[lrow * 4 + wn] = pe;
                epi_r[lrow * 4 + wn] = pr;
            }
        }
    }
    __syncthreads();
    if (t < 64) {
        int n = n0 + t;
        if (n < Nn) {
            g_el2[n] = epi_e[t * 4] + epi_e[t * 4 + 1] + epi_e[t * 4 + 2] + epi_e[t * 4 + 3];
            g_er2[n] = epi_r[t * 4] + epi_r[t * 4 + 1] + epi_r[t * 4 + 2] + epi_r[t * 4 + 3];
        }
    }
}

// ---------------- layer 2 aggregation + fused layer-3 projection -----------
__global__ void __launch_bounds__(256) agg2f_kernel(const float* __restrict__ b2,
                                                    float* __restrict__ emb,
                                                    const float* __restrict__ W3,
                                                    const float* __restrict__ al3,
                                                    const float* __restrict__ ar3) {
    __shared__ float W3s[32 * 64];
    __shared__ float al3s[64], ar3s[64];
    const int t = threadIdx.x;
#pragma unroll
    for (int i = 0; i < 8; i++) W3s[t + 256 * i] = __ldg(W3 + t + 256 * i);
    if (t < 64) { al3s[t] = __ldg(al3 + t); ar3s[t] = __ldg(ar3 + t); }
    __syncthreads();

    const int wid = (blockIdx.x * blockDim.x + t) >> 5;
    const int lane = t & 31;
    const int d = wid;
    const int rs = g_rowstart[d], re = g_rowstart[d + 1];
    const float erd = g_er2[d];
    float acc = 0.f, s = 0.f;
    int e = rs;
    for (; e + 8 <= re; e += 8) {
        int si[8];
#pragma unroll
        for (int j = 0; j < 8; j++) si[j] = g_esrc[e + j];
        float lv[8], hv[8];
#pragma unroll
        for (int j = 0; j < 8; j++) lv[j] = g_el2[si[j]];
#pragma unroll
        for (int j = 0; j < 8; j++) hv[j] = __half2float(g_h2h[(size_t)si[j] * 32 + lane]);
#pragma unroll
        for (int j = 0; j < 8; j++) {
            float ee = __expf(lrelu(lv[j] + erd));
            s += ee;
            acc = fmaf(ee, hv[j], acc);
        }
    }
    for (; e < re; e++) {
        int src = g_esrc[e];
        float ee = __expf(lrelu(g_el2[src] + erd));
        s += ee;
        acc = fmaf(ee, __half2float(g_h2h[(size_t)src * 32 + lane]), acc);
    }
    float v = (s > 0.f) ? acc / s : 0.f;
    v += __ldg(b2 + lane);
    emb[(size_t)d * 32 + lane] = v;

    float a0 = 0.f, a1 = 0.f;
#pragma unroll
    for (int k = 0; k < 32; k++) {
        float ek = __shfl_sync(0xffffffffu, v, k);
        a0 = fmaf(ek, W3s[k * 64 + lane], a0);
        a1 = fmaf(ek, W3s[k * 64 + 32 + lane], a1);
    }
    g_h3h[(size_t)d * 64 + lane]      = __float2half(a0);
    g_h3h[(size_t)d * 64 + 32 + lane] = __float2half(a1);
    float e3 = wred(a0 * al3s[lane] + a1 * al3s[32 + lane]);
    float r3 = wred(a0 * ar3s[lane] + a1 * ar3s[32 + lane]);
    if (lane == 0) { g_el3[d] = e3; g_er3[d] = r3; }
}

// ---------------- layer 3 aggregation: 8x unrolled, half2 gathers ----------
__global__ void agg3_kernel(const float* __restrict__ b3, float* __restrict__ out) {
    const int wid = (blockIdx.x * blockDim.x + threadIdx.x) >> 5;
    const int lane = threadIdx.x & 31;
    const int d = wid;
    const int rs = g_rowstart[d], re = g_rowstart[d + 1];
    const float erd = g_er3[d];
    float ax = 0.f, ay = 0.f, s = 0.f;
    int e = rs;
    for (; e + 8 <= re; e += 8) {
        int si[8];
#pragma unroll
        for (int j = 0; j < 8; j++) si[j] = g_esrc[e + j];
        float lv[8];
        __half2 hv[8];
#pragma unroll
        for (int j = 0; j < 8; j++) lv[j] = g_el3[si[j]];
#pragma unroll
        for (int j = 0; j < 8; j++) hv[j] = *((const __half2*)(g_h3h + (size_t)si[j] * 64) + lane);
#pragma unroll
        for (int j = 0; j < 8; j++) {
            float ee = __expf(lrelu(lv[j] + erd));
            s += ee;
            float2 f = __half22float2(hv[j]);
            ax = fmaf(ee, f.x, ax);
            ay = fmaf(ee, f.y, ay);
        }
    }
    for (; e < re; e++) {
        int src = g_esrc[e];
        float ee = __expf(lrelu(g_el3[src] + erd));
        s += ee;
        float2 f = __half22float2(*((const __half2*)(g_h3h + (size_t)src * 64) + lane));
        ax = fmaf(ee, f.x, ax);
        ay = fmaf(ee, f.y, ay);
    }
    float inv = (s > 0.f) ? (1.f / s) : 0.f;
    int col = 2 * lane;
    float ox = ax * inv + __ldg(b3 + col);
    float oy = ay * inv + __ldg(b3 + col + 1);
    *(float2*)&out[(size_t)d * 64 + col] = make_float2(ox, oy);
}

// ---------------- launch ----------------
extern "C" void kernel_launch(void* const* d_in, const int* in_sizes, int n_in,
                              void* d_out, int out_size) {
    const float* features = (const float*)d_in[0];
    const int*   src      = (const int*)d_in[1];
    const int*   dst      = (const int*)d_in[2];
    const float* W1  = (const float*)d_in[3];
    const float* al1 = (const float*)d_in[4];
    const float* ar1 = (const float*)d_in[5];
    const float* b1  = (const float*)d_in[6];
    const float* W2  = (const float*)d_in[7];
    const float* al2 = (const float*)d_in[8];
    const float* ar2 = (const float*)d_in[9];
    const float* b2  = (const float*)d_in[10];
    const float* W3  = (const float*)d_in[11];
    const float* al3 = (const float*)d_in[12];
    const float* ar3 = (const float*)d_in[13];
    const float* b3  = (const float*)d_in[14];

    float* out = (float*)d_out;                 // h: [N,64]
    float* emb = out + (size_t)Nn * 64;         // embedding: [N,32]

    static cudaStream_t s1 = nullptr;
    static cudaEvent_t ev_fork = nullptr, ev_gemm1 = nullptr;
    if (!s1) {
        cudaFuncSetAttribute(gemm1m_kernel, cudaFuncAttributeMaxDynamicSharedMemorySize, G1_SMEM);
        cudaFuncSetAttribute(gemm2m_kernel, cudaFuncAttributeMaxDynamicSharedMemorySize, G2_SMEM);
        cudaStreamCreate(&s1);
        cudaEventCreateWithFlags(&ev_fork, cudaEventDisableTiming);
        cudaEventCreateWithFlags(&ev_gemm1, cudaEventDisableTiming);
    }

    // Fork: branch A (s1) = weight pack + layer-1 GEMM (independent of graph)
    cudaEventRecord(ev_fork, 0);
    cudaStreamWaitEvent(s1, ev_fork, 0);
    wpack_kernel<<<160, 256, 0, s1>>>(W1, W2);
    gemm1m_kernel<<<2 * ((Nn + 63) / 64), 256, G1_SMEM, s1>>>(features, al1, ar1);
    cudaEventRecord(ev_gemm1, s1);

    // Branch B (capture stream) = CSR build
    zero_kernel<<<(Nn + 255) / 256, 256>>>();
    count_kernel<<<(Ne + 255) / 256, 256>>>(dst);
    scan_kernel<<<1, 1024>>>();
    scatter_kernel<<<(Ne + 255) / 256, 256>>>(src, dst);

    // Join
    cudaStreamWaitEvent(0, ev_gemm1, 0);

    agg1_kernel<<<Nn / 8, 256>>>(b1);
    gemm2m_kernel<<<(Nn + 63) / 64, 256, G2_SMEM>>>(al2, ar2);
    agg2f_kernel<<<Nn / 8, 256>>>(b2, emb, W3, al3, ar3);
    agg3_kernel<<<Nn / 8, 256>>>(b3, out);
}

// round 13
// speedup vs baseline: 1.0061x; 1.0061x over previous
#include <cuda_runtime.h>
#include <cuda_fp16.h>
#include <cuda_bf16.h>

#define Nn 50000
#define Ne 800000
// IN=128, H1=8, HID=32, OUT=64

// ---------------- device scratch ----------------
__device__ __half g_h1h[(size_t)Nn * 256];  // layer1 features fp16 [N,8,32]
__device__ float g_x1[(size_t)Nn * 256];    // layer1 output (relu) = layer2 input
__device__ float g_el1[Nn * 8], g_er1[Nn * 8];
__device__ __half g_h2h[(size_t)Nn * 32];
__device__ float g_el2[Nn], g_er2[Nn];
__device__ __half g_h3h[(size_t)Nn * 64];
__device__ float g_el3[Nn], g_er3[Nn];

__device__ int g_deg[Nn];
__device__ int g_fill[Nn];
__device__ int g_rowstart[Nn + 1];
__device__ int g_esrc[Ne];

__device__ unsigned g_wpk[128 * 256];      // W1 packed bf16 hi|lo
__device__ unsigned g_wpk2[256 * 32];      // W2 packed bf16 hi|lo

// ---------------- helpers ----------------
__device__ __forceinline__ float wred(float v) {
#pragma unroll
    for (int o = 16; o > 0; o >>= 1) v += __shfl_xor_sync(0xffffffffu, v, o);
    return v;
}

__device__ __forceinline__ float lrelu(float x) {
    return x > 0.f ? x : 0.2f * x;
}

__device__ __forceinline__ void mma16816(float c[4], unsigned a0, unsigned a1,
                                         unsigned a2, unsigned a3,
                                         unsigned b0, unsigned b1) {
    asm volatile(
        "mma.sync.aligned.m16n8k16.row.col.f32.bf16.bf16.f32 "
        "{%0,%1,%2,%3}, {%4,%5,%6,%7}, {%8,%9}, {%0,%1,%2,%3};\n"
        : "+f"(c[0]), "+f"(c[1]), "+f"(c[2]), "+f"(c[3])
        : "r"(a0), "r"(a1), "r"(a2), "r"(a3), "r"(b0), "r"(b1));
}

__device__ __forceinline__ unsigned packw(float v) {
    __nv_bfloat16 h = __float2bfloat16(v);
    float hf = __bfloat162float(h);
    __nv_bfloat16 l = __float2bfloat16(v - hf);
    return (unsigned)__bfloat16_as_ushort(h) | ((unsigned)__bfloat16_as_ushort(l) << 16);
}

// ---------------- CSR build ----------------
__global__ void zero_kernel() {
    int i = blockIdx.x * blockDim.x + threadIdx.x;
    if (i < Nn) { g_deg[i] = 0; g_fill[i] = 0; }
}

__global__ void count_kernel(const int* __restrict__ dst) {
    int e = blockIdx.x * blockDim.x + threadIdx.x;
    if (e < Ne) atomicAdd(&g_deg[dst[e]], 1);
}

__global__ void scan_kernel() {
    __shared__ int warpsum[32];
    const int t = threadIdx.x;            // 1024
    const int lane = t & 31, wid = t >> 5;
    const int CH = (Nn + 1023) / 1024;
    const int base = t * CH;
    int sum = 0;
#pragma unroll 1
    for (int i = 0; i < CH; i++) {
        int idx = base + i;
        if (idx < Nn) sum += g_deg[idx];
    }
    int v = sum;
#pragma unroll
    for (int o = 1; o < 32; o <<= 1) {
        int u = __shfl_up_sync(0xffffffffu, v, o);
        if (lane >= o) v += u;
    }
    if (lane == 31) warpsum[wid] = v;
    __syncthreads();
    if (wid == 0) {
        int w = warpsum[lane];
        int vv = w;
#pragma unroll
        for (int o = 1; o < 32; o <<= 1) {
            int u = __shfl_up_sync(0xffffffffu, vv, o);
            if (lane >= o) vv += u;
        }
        warpsum[lane] = vv;
    }
    __syncthreads();
    int excl = v - sum + (wid > 0 ? warpsum[wid - 1] : 0);
    int run = excl;
#pragma unroll 1
    for (int i = 0; i < CH; i++) {
        int idx = base + i;
        if (idx < Nn) { g_rowstart[idx] = run; run += g_deg[idx]; }
    }
    if (t == 1023) g_rowstart[Nn] = run;
}

__global__ void scatter_kernel(const int* __restrict__ src, const int* __restrict__ dst) {
    int e = blockIdx.x * blockDim.x + threadIdx.x;
    if (e >= Ne) return;
    int d = dst[e];
    int pos = g_rowstart[d] + atomicAdd(&g_fill[d], 1);
    g_esrc[pos] = src[e];
}

// ---------------- W packing (bf16 hi/lo), both weights ----------------
__global__ void wpack_kernel(const float* __restrict__ W1, const float* __restrict__ W2) {
    int i = blockIdx.x * blockDim.x + threadIdx.x;   // 40960
    float w;
    if (i < 32768) w = W1[i];
    else           w = W2[i - 32768];
    unsigned p = packw(w);
    if (i < 32768) g_wpk[i] = p;
    else           g_wpk2[i - 32768] = p;
}

// ---------------- layer 1 GEMM: TC bf16-split, compact A, N-split, 2 CTA/SM ----
#define A_STRIDE 132           // bank(4g+tr) conflict-free for A frag loads
#define B1_STRIDE 136          // bank(8tr+g) conflict-free for B frag loads
#define G1_SMEM ((64 * A_STRIDE + 128 * B1_STRIDE) * 4)   // 103424 B

__global__ void __launch_bounds__(256, 2) gemm1m_kernel(const float* __restrict__ X,
                                                        const float* __restrict__ al,
                                                        const float* __restrict__ ar) {
    extern __shared__ unsigned smem[];
    unsigned* Ac = smem;                         // compact (ah|al) [64][A_STRIDE]
    unsigned* B  = smem + 64 * A_STRIDE;         // (bh,bl) [128 k][B1_STRIDE], half N

    const int t = threadIdx.x;
    const int n0 = (blockIdx.x >> 1) * 64;       // row tile
    const int nb = (blockIdx.x & 1) * 128;       // col half

    // stage A: 64 x 128 fp32 -> compact packed words
#pragma unroll
    for (int i = 0; i < 8; i++) {
        int idx = t + 256 * i;                   // float4 index, 2048 total
        int row = idx >> 5, c4 = idx & 31;
        int grow = n0 + row;
        float4 v = (grow < Nn) ? __ldg((const float4*)(X + (size_t)grow * 128) + c4)
                               : make_float4(0.f, 0.f, 0.f, 0.f);
        uint4 p = make_uint4(packw(v.x), packw(v.y), packw(v.z), packw(v.w));
        *(uint4*)&Ac[row * A_STRIDE + c4 * 4] = p;
    }
    // stage B: copy pre-packed W1 columns [nb, nb+128)
#pragma unroll
    for (int i = 0; i < 16; i++) {
        int idx = t + 256 * i;                   // uint4 index, 4096 total
        int row = idx >> 5, c4 = idx & 31;
        uint4 v = *((const uint4*)(g_wpk + row * 256 + nb) + c4);
        *(uint4*)&B[row * B1_STRIDE + c4 * 4] = v;
    }
    __syncthreads();

    const int warp = t >> 5, lane = t & 31;
    const int wm = warp >> 2, wn = warp & 3;     // 2 (M:32 rows) x 4 (N:32 cols)
    const int g = lane >> 2, tr = lane & 3;

    float c[2][4][4] = {};
#pragma unroll 1
    for (int ks = 0; ks < 16; ks++) {
        int kb = ks * 8;
        unsigned b0[4], b1[4];
#pragma unroll
        for (int nt = 0; nt < 4; nt++) {
            int colL = wn * 32 + nt * 8 + g;
            b0[nt] = B[(kb + tr) * B1_STRIDE + colL];
            b1[nt] = B[(kb + 4 + tr) * B1_STRIDE + colL];
        }
#pragma unroll
        for (int mt = 0; mt < 2; mt++) {
            int rb = wm * 32 + mt * 16;
            unsigned aw0 = Ac[(rb + g) * A_STRIDE + kb + tr];
            unsigned aw1 = Ac[(rb + 8 + g) * A_STRIDE + kb + tr];
            unsigned aw2 = Ac[(rb + g) * A_STRIDE + kb + 4 + tr];
            unsigned aw3 = Ac[(rb + 8 + g) * A_STRIDE + kb + 4 + tr];
            // hi pass: (ah,ah) x (bh,bl)
            unsigned h0 = __byte_perm(aw0, aw0, 0x1010);
            unsigned h1 = __byte_perm(aw1, aw1, 0x1010);
            unsigned h2 = __byte_perm(aw2, aw2, 0x1010);
            unsigned h3 = __byte_perm(aw3, aw3, 0x1010);
#pragma unroll
            for (int nt = 0; nt < 4; nt++)
                mma16816(c[mt][nt], h0, h1, h2, h3, b0[nt], b1[nt]);
            // lo pass: (al,al) x (bh,bl)
            unsigned l0 = __byte_perm(aw0, aw0, 0x3232);
            unsigned l1 = __byte_perm(aw1, aw1, 0x3232);
            unsigned l2 = __byte_perm(aw2, aw2, 0x3232);
            unsigned l3 = __byte_perm(aw3, aw3, 0x3232);
#pragma unroll
            for (int nt = 0; nt < 4; nt++)
                mma16816(c[mt][nt], l0, l1, l2, l3, b0[nt], b1[nt]);
        }
    }

    // epilogue: store fp16 h1 + per-head el/er (this warp = head (nb/32 + wn))
    const int head = (nb >> 5) + wn;
    float alv[4][2], arv[4][2];
#pragma unroll
    for (int nt = 0; nt < 4; nt++) {
        int col = nb + wn * 32 + nt * 8 + tr * 2;
        alv[nt][0] = __ldg(al + col);  alv[nt][1] = __ldg(al + col + 1);
        arv[nt][0] = __ldg(ar + col);  arv[nt][1] = __ldg(ar + col + 1);
    }
#pragma unroll
    for (int mt = 0; mt < 2; mt++) {
#pragma unroll
        for (int half = 0; half < 2; half++) {
            int r = n0 + wm * 32 + mt * 16 + g + 8 * half;
            float pe = 0.f, pr = 0.f;
#pragma unroll
            for (int nt = 0; nt < 4; nt++) {
                float c0 = c[mt][nt][2 * half], c1 = c[mt][nt][2 * half + 1];
                int col = nb + wn * 32 + nt * 8 + tr * 2;
                if (r < Nn)
                    *(__half2*)&g_h1h[(size_t)r * 256 + col] = __floats2half2_rn(c0, c1);
                pe += c0 * alv[nt][0] + c1 * alv[nt][1];
                pr += c0 * arv[nt][0] + c1 * arv[nt][1];
            }
            pe += __shfl_xor_sync(0xffffffffu, pe, 1);
            pe += __shfl_xor_sync(0xffffffffu, pe, 2);
            pr += __shfl_xor_sync(0xffffffffu, pr, 1);
            pr += __shfl_xor_sync(0xffffffffu, pr, 2);
            if (tr == 0 && r < Nn) {
                g_el1[r * 8 + head] = pe;
                g_er1[r * 8 + head] = pr;
            }
        }
    }
}

// ---------------- layer 1 aggregation: warp/dst, 4x unrolled gather --------
__global__ void agg1_kernel(const float* __restrict__ b1) {
    const int wid = (blockIdx.x * blockDim.x + threadIdx.x) >> 5;
    const int lane = threadIdx.x & 31;
    const int d = wid;
    const int rs = g_rowstart[d], re = g_rowstart[d + 1];
    const float erh = (lane < 8) ? g_er1[d * 8 + lane] : 0.f;
    const int h0 = lane >> 4;
    float2 acc[4] = {{0, 0}, {0, 0}, {0, 0}, {0, 0}};
    float s = 0.f;
    int e = rs;
    for (; e + 4 <= re; e += 4) {
        int s0 = g_esrc[e], s1 = g_esrc[e + 1], s2 = g_esrc[e + 2], s3 = g_esrc[e + 3];
        float l0 = 0.f, l1 = 0.f, l2 = 0.f, l3 = 0.f;
        if (lane < 8) {
            l0 = g_el1[s0 * 8 + lane]; l1 = g_el1[s1 * 8 + lane];
            l2 = g_el1[s2 * 8 + lane]; l3 = g_el1[s3 * 8 + lane];
        }
        const __half2* p0 = (const __half2*)(g_h1h + (size_t)s0 * 256);
        const __half2* p1 = (const __half2*)(g_h1h + (size_t)s1 * 256);
        const __half2* p2 = (const __half2*)(g_h1h + (size_t)s2 * 256);
        const __half2* p3 = (const __half2*)(g_h1h + (size_t)s3 * 256);
        __half2 v0[4], v1[4], v2[4], v3[4];
#pragma unroll
        for (int q = 0; q < 4; q++) v0[q] = p0[q * 32 + lane];
#pragma unroll
        for (int q = 0; q < 4; q++) v1[q] = p1[q * 32 + lane];
#pragma unroll
        for (int q = 0; q < 4; q++) v2[q] = p2[q * 32 + lane];
#pragma unroll
        for (int q = 0; q < 4; q++) v3[q] = p3[q * 32 + lane];
        float e0 = 0.f, e1 = 0.f, e2 = 0.f, e3 = 0.f;
        if (lane < 8) {
            e0 = __expf(lrelu(l0 + erh)); e1 = __expf(lrelu(l1 + erh));
            e2 = __expf(lrelu(l2 + erh)); e3 = __expf(lrelu(l3 + erh));
            s += (e0 + e1) + (e2 + e3);
        }
#pragma unroll
        for (int q = 0; q < 4; q++) {
            int hsel = 2 * q + h0;
            float w0 = __shfl_sync(0xffffffffu, e0, hsel);
            float w1 = __shfl_sync(0xffffffffu, e1, hsel);
            float w2 = __shfl_sync(0xffffffffu, e2, hsel);
            float w3 = __shfl_sync(0xffffffffu, e3, hsel);
            float2 f0 = __half22float2(v0[q]), f1 = __half22float2(v1[q]);
            float2 f2 = __half22float2(v2[q]), f3 = __half22float2(v3[q]);
            acc[q].x = fmaf(w0, f0.x, fmaf(w1, f1.x, fmaf(w2, f2.x, fmaf(w3, f3.x, acc[q].x))));
            acc[q].y = fmaf(w0, f0.y, fmaf(w1, f1.y, fmaf(w2, f2.y, fmaf(w3, f3.y, acc[q].y))));
        }
    }
    for (; e < re; e++) {
        int src = g_esrc[e];
        float ee = 0.f;
        if (lane < 8) {
            ee = __expf(lrelu(g_el1[src * 8 + lane] + erh));
            s += ee;
        }
        const __half2* hp = (const __half2*)(g_h1h + (size_t)src * 256);
#pragma unroll
        for (int q = 0; q < 4; q++) {
            float eh = __shfl_sync(0xffffffffu, ee, 2 * q + h0);
            float2 f = __half22float2(hp[q * 32 + lane]);
            acc[q].x = fmaf(eh, f.x, acc[q].x);
            acc[q].y = fmaf(eh, f.y, acc[q].y);
        }
    }
#pragma unroll
    for (int q = 0; q < 4; q++) {
        float sh = __shfl_sync(0xffffffffu, s, 2 * q + h0);
        float inv = (sh > 0.f) ? (1.f / sh) : 0.f;
        int col = 64 * q + 2 * lane;
        float vx = fmaxf(acc[q].x * inv + __ldg(b1 + col), 0.f);
        float vy = fmaxf(acc[q].y * inv + __ldg(b1 + col + 1), 0.f);
        *(float2*)&g_x1[(size_t)d * 256 + col] = make_float2(vx, vy);
    }
}

// ---------------- layer 2 GEMM: TC bf16-split, compact A, 2 CTA/SM ---------
#define A2_STRIDE 260
#define B2_STRIDE 40
#define G2_SMEM ((64 * A2_STRIDE + 256 * B2_STRIDE) * 4)   // 107520 B

__global__ void __launch_bounds__(256, 2) gemm2m_kernel(const float* __restrict__ al,
                                                        const float* __restrict__ ar) {
    extern __shared__ unsigned smem[];
    unsigned* Ac = smem;                         // compact [64][A2_STRIDE]
    unsigned* B  = smem + 64 * A2_STRIDE;        // [256 k][B2_STRIDE]

    const int t = threadIdx.x;
    const int n0 = blockIdx.x * 64;

#pragma unroll
    for (int i = 0; i < 16; i++) {
        int idx = t + 256 * i;                   // float4 index, 4096 total
        int row = idx >> 6, c4 = idx & 63;
        int grow = n0 + row;
        float4 v = (grow < Nn) ? *((const float4*)(g_x1 + (size_t)grow * 256) + c4)
                               : make_float4(0.f, 0.f, 0.f, 0.f);
        uint4 p = make_uint4(packw(v.x), packw(v.y), packw(v.z), packw(v.w));
        *(uint4*)&Ac[row * A2_STRIDE + c4 * 4] = p;
    }
#pragma unroll
    for (int i = 0; i < 8; i++) {
        int idx = t + 256 * i;                   // uint4 index, 2048 total
        int row = idx >> 3, c4 = idx & 7;
        uint4 v = *((const uint4*)g_wpk2 + idx);
        *(uint4*)&B[row * B2_STRIDE + c4 * 4] = v;
    }
    __syncthreads();

    const int warp = t >> 5, lane = t & 31;
    const int wm = warp >> 2, wn = warp & 3;
    const int g = lane >> 2, tr = lane & 3;

    float c[2][4] = {};
#pragma unroll 1
    for (int ks = 0; ks < 32; ks++) {
        int kb = ks * 8;
        int col = wn * 8 + g;
        unsigned b0 = B[(kb + tr) * B2_STRIDE + col];
        unsigned b1 = B[(kb + 4 + tr) * B2_STRIDE + col];
#pragma unroll
        for (int mt = 0; mt < 2; mt++) {
            int rb = wm * 32 + mt * 16;
            unsigned aw0 = Ac[(rb + g) * A2_STRIDE + kb + tr];
            unsigned aw1 = Ac[(rb + 8 + g) * A2_STRIDE + kb + tr];
            unsigned aw2 = Ac[(rb + g) * A2_STRIDE + kb + 4 + tr];
            unsigned aw3 = Ac[(rb + 8 + g) * A2_STRIDE + kb + 4 + tr];
            unsigned h0 = __byte_perm(aw0, aw0, 0x1010);
            unsigned h1 = __byte_perm(aw1, aw1, 0x1010);
            unsigned h2 = __byte_perm(aw2, aw2, 0x1010);
            unsigned h3 = __byte_perm(aw3, aw3, 0x1010);
            mma16816(c[mt], h0, h1, h2, h3, b0, b1);
            unsigned l0 = __byte_perm(aw0, aw0, 0x3232);
            unsigned l1 = __byte_perm(aw1, aw1, 0x3232);
            unsigned l2 = __byte_perm(aw2, aw2, 0x3232);
            unsigned l3 = __byte_perm(aw3, aw3, 0x3232);
            mma16816(c[mt], l0, l1, l2, l3, b0, b1);
        }
    }
    __syncthreads();

    float* epi_e = (float*)smem;          // [64][4]
    float* epi_r = (float*)smem + 256;

    const int col = wn * 8 + tr * 2;
    const float a0v = __ldg(al + col), a1v = __ldg(al + col + 1);
    const float r0v = __ldg(ar + col), r1v = __ldg(ar + col + 1);

#pragma unroll
    for (int mt = 0; mt < 2; mt++) {
#pragma unroll
        for (int half = 0; half < 2; half++) {
            int lrow = wm * 32 + mt * 16 + g + 8 * half;
            int r = n0 + lrow;
            float c0 = c[mt][2 * half], c1 = c[mt][2 * half + 1];
            if (r < Nn)
                *(__half2*)&g_h2h[(size_t)r * 32 + col] = __floats2half2_rn(c0, c1);
            float pe = c0 * a0v + c1 * a1v;
            float pr = c0 * r0v + c1 * r1v;
            pe += __shfl_xor_sync(0xffffffffu, pe, 1);
            pe += __shfl_xor_sync(0xffffffffu, pe, 2);
            pr += __shfl_xor_sync(0xffffffffu, pr, 1);
            pr += __shfl_xor_sync(0xffffffffu, pr, 2);
            if (tr == 0) {
                epi_e[lrow * 4 + wn] = pe;
                epi_r[lrow * 4 + wn] = pr;
            }
        }
    }
    __syncthreads();
    if (t < 64) {
        int n = n0 + t;
        if (n < Nn) {
            g_el2[n] = epi_e[t * 4] + epi_e[t * 4 + 1] + epi_e[t * 4 + 2] + epi_e[t * 4 + 3];
            g_er2[n] = epi_r[t * 4] + epi_r[t * 4 + 1] + epi_r[t * 4 + 2] + epi_r[t * 4 + 3];
        }
    }
}

// ---------------- layer 2 aggregation + fused layer-3 projection -----------
__global__ void __launch_bounds__(256) agg2f_kernel(const float* __restrict__ b2,
                                                    float* __restrict__ emb,
                                                    const float* __restrict__ W3,
                                                    const float* __restrict__ al3,
                                                    const float* __restrict__ ar3) {
    __shared__ float W3s[32 * 64];
    __shared__ float al3s[64], ar3s[64];
    const int t = threadIdx.x;
#pragma unroll
    for (int i = 0; i < 8; i++) W3s[t + 256 * i] = __ldg(W3 + t + 256 * i);
    if (t < 64) { al3s[t] = __ldg(al3 + t); ar3s[t] = __ldg(ar3 + t); }
    __syncthreads();

    const int wid = (blockIdx.x * blockDim.x + t) >> 5;
    const int lane = t & 31;
    const int d = wid;
    const int rs = g_rowstart[d], re = g_rowstart[d + 1];
    const float erd = g_er2[d];
    float acc = 0.f, s = 0.f;
    int e = rs;
    for (; e + 8 <= re; e += 8) {
        int si[8];
#pragma unroll
        for (int j = 0; j < 8; j++) si[j] = g_esrc[e + j];
        float lv[8], hv[8];
#pragma unroll
        for (int j = 0; j < 8; j++) lv[j] = g_el2[si[j]];
#pragma unroll
        for (int j = 0; j < 8; j++) hv[j] = __half2float(g_h2h[(size_t)si[j] * 32 + lane]);
#pragma unroll
        for (int j = 0; j < 8; j++) {
            float ee = __expf(lrelu(lv[j] + erd));
            s += ee;
            acc = fmaf(ee, hv[j], acc);
        }
    }
    for (; e < re; e++) {
        int src = g_esrc[e];
        float ee = __expf(lrelu(g_el2[src] + erd));
        s += ee;
        acc = fmaf(ee, __half2float(g_h2h[(size_t)src * 32 + lane]), acc);
    }
    float v = (s > 0.f) ? acc / s : 0.f;
    v += __ldg(b2 + lane);
    emb[(size_t)d * 32 + lane] = v;

    float a0 = 0.f, a1 = 0.f;
#pragma unroll
    for (int k = 0; k < 32; k++) {
        float ek = __shfl_sync(0xffffffffu, v, k);
        a0 = fmaf(ek, W3s[k * 64 + lane], a0);
        a1 = fmaf(ek, W3s[k * 64 + 32 + lane], a1);
    }
    g_h3h[(size_t)d * 64 + lane]      = __float2half(a0);
    g_h3h[(size_t)d * 64 + 32 + lane] = __float2half(a1);
    float e3 = wred(a0 * al3s[lane] + a1 * al3s[32 + lane]);
    float r3 = wred(a0 * ar3s[lane] + a1 * ar3s[32 + lane]);
    if (lane == 0) { g_el3[d] = e3; g_er3[d] = r3; }
}

// ---------------- layer 3 aggregation: 8x unrolled, half2 gathers ----------
__global__ void agg3_kernel(const float* __restrict__ b3, float* __restrict__ out) {
    const int wid = (blockIdx.x * blockDim.x + threadIdx.x) >> 5;
    const int lane = threadIdx.x & 31;
    const int d = wid;
    const int rs = g_rowstart[d], re = g_rowstart[d + 1];
    const float erd = g_er3[d];
    float ax = 0.f, ay = 0.f, s = 0.f;
    int e = rs;
    for (; e + 8 <= re; e += 8) {
        int si[8];
#pragma unroll
        for (int j = 0; j < 8; j++) si[j] = g_esrc[e + j];
        float lv[8];
        __half2 hv[8];
#pragma unroll
        for (int j = 0; j < 8; j++) lv[j] = g_el3[si[j]];
#pragma unroll
        for (int j = 0; j < 8; j++) hv[j] = *((const __half2*)(g_h3h + (size_t)si[j] * 64) + lane);
#pragma unroll
        for (int j = 0; j < 8; j++) {
            float ee = __expf(lrelu(lv[j] + erd));
            s += ee;
            float2 f = __half22float2(hv[j]);
            ax = fmaf(ee, f.x, ax);
            ay = fmaf(ee, f.y, ay);
        }
    }
    for (; e < re; e++) {
        int src = g_esrc[e];
        float ee = __expf(lrelu(g_el3[src] + erd));
        s += ee;
        float2 f = __half22float2(*((const __half2*)(g_h3h + (size_t)src * 64) + lane));
        ax = fmaf(ee, f.x, ax);
        ay = fmaf(ee, f.y, ay);
    }
    float inv = (s > 0.f) ? (1.f / s) : 0.f;
    int col = 2 * lane;
    float ox = ax * inv + __ldg(b3 + col);
    float oy = ay * inv + __ldg(b3 + col + 1);
    *(float2*)&out[(size_t)d * 64 + col] = make_float2(ox, oy);
}

// ---------------- launch ----------------
extern "C" void kernel_launch(void* const* d_in, const int* in_sizes, int n_in,
                              void* d_out, int out_size) {
    const float* features = (const float*)d_in[0];
    const int*   src      = (const int*)d_in[1];
    const int*   dst      = (const int*)d_in[2];
    const float* W1  = (const float*)d_in[3];
    const float* al1 = (const float*)d_in[4];
    const float* ar1 = (const float*)d_in[5];
    const float* b1  = (const float*)d_in[6];
    const float* W2  = (const float*)d_in[7];
    const float* al2 = (const float*)d_in[8];
    const float* ar2 = (const float*)d_in[9];
    const float* b2  = (const float*)d_in[10];
    const float* W3  = (const float*)d_in[11];
    const float* al3 = (const float*)d_in[12];
    const float* ar3 = (const float*)d_in[13];
    const float* b3  = (const float*)d_in[14];

    float* out = (float*)d_out;                 // h: [N,64]
    float* emb = out + (size_t)Nn * 64;         // embedding: [N,32]

    static cudaStream_t s1 = nullptr;
    static cudaEvent_t ev_fork = nullptr, ev_gemm1 = nullptr;
    if (!s1) {
        cudaFuncSetAttribute(gemm1m_kernel, cudaFuncAttributeMaxDynamicSharedMemorySize, G1_SMEM);
        cudaFuncSetAttribute(gemm2m_kernel, cudaFuncAttributeMaxDynamicSharedMemorySize, G2_SMEM);
        cudaStreamCreate(&s1);
        cudaEventCreateWithFlags(&ev_fork, cudaEventDisableTiming);
        cudaEventCreateWithFlags(&ev_gemm1, cudaEventDisableTiming);
    }

    // Fork: branch A (s1) = weight pack + layer-1 GEMM (independent of graph)
    cudaEventRecord(ev_fork, 0);
    cudaStreamWaitEvent(s1, ev_fork, 0);
    wpack_kernel<<<160, 256, 0, s1>>>(W1, W2);
    gemm1m_kernel<<<2 * ((Nn + 63) / 64), 256, G1_SMEM, s1>>>(features, al1, ar1);
    cudaEventRecord(ev_gemm1, s1);

    // Branch B (capture stream) = CSR build
    zero_kernel<<<(Nn + 255) / 256, 256>>>();
    count_kernel<<<(Ne + 255) / 256, 256>>>(dst);
    scan_kernel<<<1, 1024>>>();
    scatter_kernel<<<(Ne + 255) / 256, 256>>>(src, dst);

    // Join
    cudaStreamWaitEvent(0, ev_gemm1, 0);

    agg1_kernel<<<Nn / 8, 256>>>(b1);
    gemm2m_kernel<<<(Nn + 63) / 64, 256, G2_SMEM>>>(al2, ar2);
    agg2f_kernel<<<Nn / 8, 256>>>(b2, emb, W3, al3, ar3);
    agg3_kernel<<<Nn / 8, 256>>>(b3, out);
}